// round 16
// baseline (speedup 1.0000x reference)
#include <cuda_runtime.h>
#include <cuda_bf16.h>

// PatchEmbed: x (16,64,256,256) f32 -> out (16, 16384, 256) f32  + 4-float shape tail
//
// out[n][j*128 + i][c*4 + ph*2 + pw] = x[n][c][2*i + ph][2*j + pw]
//
// Measured gradient (kernel us / DRAM%):
//   R10: 8192 CTAs x 256thr, 33KB smem  -> 97.8 / 62.9
//   R11: 16384 CTAs x 512thr, 17KB smem -> 80.5 / 76.7
//   R8 : 32768 CTAs x 256thr, 8.4KB     -> 76.7 / 79.6
// More, smaller CTAs = better phase mixing (concurrent reads+writes in
// flight across HBM turnarounds). This kernel tests one notch further:
//   65536 CTAs x 128thr, 32(r)x16(j) float2 tile, 4.4KB smem, 16 CTAs/SM.
//
// float2-unit strides:
//   input : n: 2097152, c: 32768, i: 256, ph: 128, j: 1
//   output: n: 2097152, j: 16384, i: 128, r: 1

#define TR 32
#define TJ 16
#define PAD 1   // row stride 17 float2 -> 2-way LDS conflict on column reads

__global__ __launch_bounds__(128)
void patch_transpose_kernel(const float4* __restrict__ x,
                            float4* __restrict__ out,
                            float* __restrict__ tail,   // null if absent
                            long tail_base) {
    __shared__ float2 tile[TR][TJ + PAD];

    const int t     = blockIdx.x;      // 0..31 : 8 j-tiles x 4 r-tiles
    const int tj    = t & 7;
    const int tr    = t >> 3;
    const int plane = blockIdx.y;      // n*128 + i
    const int n     = plane >> 7;
    const int i     = plane & 127;
    const int tid   = threadIdx.x;     // 0..127

    if (tail && t == 0 && plane == 0 && tid == 0) {
        tail[tail_base + 0] = 16.0f;
        tail[tail_base + 1] = 64.0f;
        tail[tail_base + 2] = 256.0f;
        tail[tail_base + 3] = 256.0f;
    }

    // ---- Load: 32 r-rows x 16 j (float2); 128B contiguous per row ----
    {
        const int  rloc = tid >> 2;            // 0..31
        const int  cf4  = tid & 3;             // 0..3
        const int  r    = tr * TR + rloc;      // r = c*2 + ph
        const int  c    = r >> 1;
        const int  ph   = r & 1;
        const long in_f4 = ((long)n * 2097152 + (long)i * 256
                            + (long)c * 32768 + ph * 128) >> 1;
        #pragma unroll
        for (int k = 0; k < 2; k++) {
            const int colf4 = cf4 + k * 4;                // 0..7 within tile
            float4 v = x[in_f4 + tj * 8 + colf4];
            tile[rloc][colf4 * 2 + 0] = make_float2(v.x, v.y);
            tile[rloc][colf4 * 2 + 1] = make_float2(v.z, v.w);
        }
    }
    __syncthreads();

    // ---- Store: 16 j-rows, 256B contiguous r-chunk each ----
    {
        const int  r2   = tid & 15;            // float4 index along r (0..15)
        const int  jrow = tid >> 4;            // 0..7
        const long out_base_f4 = ((long)n * 2097152 + (long)i * 128) >> 1;
        #pragma unroll
        for (int k = 0; k < 2; k++) {
            const int jl = jrow + k * 8;       // 0..15 within tile
            const int j  = tj * TJ + jl;
            float2 a = tile[r2 * 2 + 0][jl];
            float2 b = tile[r2 * 2 + 1][jl];
            out[out_base_f4 + (long)j * 8192 + tr * 16 + r2] =
                make_float4(a.x, a.y, b.x, b.y);
        }
    }
}

extern "C" void kernel_launch(void* const* d_in, const int* in_sizes, int n_in,
                              void* d_out, int out_size) {
    const float4* x = (const float4*)d_in[0];
    float4* out     = (float4*)d_out;

    const long main_elems = 16L * 16384L * 256L;  // 67108864 floats
    float* tail = ((long)out_size >= main_elems + 4) ? (float*)d_out : nullptr;

    dim3 grid(32, 2048, 1);   // 32 tiles/plane, 16*128 planes
    dim3 block(128, 1, 1);
    patch_transpose_kernel<<<grid, block>>>(x, out, tail, main_elems);
}

// round 17
// speedup vs baseline: 1.0293x; 1.0293x over previous
#include <cuda_runtime.h>
#include <cuda_bf16.h>

// PatchEmbed: x (16,64,256,256) f32 -> out (16, 16384, 256) f32  + 4-float shape tail
//
// out[n][j*128 + i][c*4 + ph*2 + pw] = x[n][c][2*i + ph][2*j + pw]
//
// CHAMPION (R8 config, reverted after concurrency sweep):
//   ctx/SM:  4 -> 76.7% DRAM | 6(33KB) -> 62.9% | 8 -> 79.6% (BEST) | 16 -> 74.4%
//   kernel:  80.5us          | 97.8us           | 76.7us            | 82.8us
// 32x32 float2 tile, 256 thr, 8.4KB smem, 8 CTAs/SM, 32768 CTAs.
// Both global sides float4-coalesced; padded smem tile (2-way LDS conflicts).
//
// float2-unit strides:
//   input : n: 2097152, c: 32768, i: 256, ph: 128, j: 1
//   output: n: 2097152, j: 16384, i: 128, r: 1
//
// ori_shape tail (harness packs int32 reference into the float32 d_out
// buffer -> write AS FLOATS) folded into block (0,0): single graph node.

#define TILE 32

__global__ void patch_transpose_kernel(const float4* __restrict__ x,
                                       float4* __restrict__ out,
                                       float* __restrict__ tail,   // null if absent
                                       long tail_base) {
    // tile[r][j] in float2 units, +1 float2 padding per row
    __shared__ float2 tile[TILE][TILE + 1];

    const int t     = blockIdx.x;      // 0..15 : 4 j-tiles x 4 r-tiles
    const int tj    = t & 3;
    const int tr    = t >> 2;
    const int plane = blockIdx.y;      // n*128 + i
    const int n     = plane >> 7;
    const int i     = plane & 127;

    const int tx = threadIdx.x;        // 0..31
    const int ty = threadIdx.y;        // 0..7

    // ori_shape tail: one thread of one block
    if (tail && blockIdx.x == 0 && blockIdx.y == 0 && tx == 0 && ty == 0) {
        tail[tail_base + 0] = 16.0f;
        tail[tail_base + 1] = 64.0f;
        tail[tail_base + 2] = 256.0f;
        tail[tail_base + 3] = 256.0f;
    }

    // lane -> (row 0..15, half-row col pair 0..15) for float4 transactions
    const int lrow = (ty * 32 + tx) >> 4;          // 0..15
    const int lcol = tx & 15;                      // 0..15 (x2 float2s)

    // ---- Load phase: rows = r (strided), cols = j (contiguous, float4) ----
    {
        const long in_base_f4 = ((long)n * 2097152 + (long)i * 256) >> 1; // float4 units
        #pragma unroll
        for (int k = 0; k < 2; k++) {
            const int r  = tr * TILE + lrow + k * 16;  // r = c*2 + ph
            const int c  = r >> 1;
            const int ph = r & 1;
            const int j2 = tj * (TILE / 2) + lcol;     // float4 index along j
            float4 v = x[in_base_f4 + ((long)c * 32768 + ph * 128) / 2 + j2];
            tile[r - tr * TILE][lcol * 2 + 0] = make_float2(v.x, v.y);
            tile[r - tr * TILE][lcol * 2 + 1] = make_float2(v.z, v.w);
        }
    }
    __syncthreads();

    // ---- Store phase: rows = j (strided), cols = r (contiguous, float4) ----
    {
        const long out_base_f4 = ((long)n * 2097152 + (long)i * 128) >> 1; // float4 units
        #pragma unroll
        for (int k = 0; k < 2; k++) {
            const int j  = tj * TILE + lrow + k * 16;
            const int r2 = lcol;                        // float4 index along r within tile
            float2 a = tile[r2 * 2 + 0][j - tj * TILE];
            float2 b = tile[r2 * 2 + 1][j - tj * TILE];
            float4 v = make_float4(a.x, a.y, b.x, b.y);
            out[out_base_f4 + ((long)j * 16384) / 2 + tr * (TILE / 2) + r2] = v;
        }
    }
}

extern "C" void kernel_launch(void* const* d_in, const int* in_sizes, int n_in,
                              void* d_out, int out_size) {
    const float4* x = (const float4*)d_in[0];
    float4* out     = (float4*)d_out;

    const long main_elems = 16L * 16384L * 256L;  // 67108864 floats
    float* tail = ((long)out_size >= main_elems + 4) ? (float*)d_out : nullptr;

    dim3 grid(16, 2048, 1);   // 16 tiles/plane, 16*128 planes
    dim3 block(32, 8, 1);
    patch_transpose_kernel<<<grid, block>>>(x, out, tail, main_elems);
}